// round 5
// baseline (speedup 1.0000x reference)
#include <cuda_runtime.h>
#include <cuda_fp16.h>
#include <math.h>

#define NNODES 100000
#define EDGES  3200000
#define HDIM   128
#define EDIM   16
#define PTYPES 6

// ---- __device__ scratch (allocations are banned) ----
__device__ int    g_cnt[NNODES];        // degree histogram
__device__ int    g_rowptr[NNODES + 1]; // CSR row pointers
__device__ int    g_rowpos[NNODES];     // scatter cursors
__device__ int    g_col_s[EDGES];       // CSR-ordered packed (col | ptype<<24)
__device__ float  g_e0[EDGES];          // exp(s0) per CSR slot
__device__ float  g_d0[NNODES];         // sum exp(s0) per row
__device__ float  g_d1[NNODES];         // sum exp(s1) per row
__device__ __half g_kh[NNODES * HDIM];  // fp16 k * 1/sqrt(H)      (25.6 MB)
__device__ __half g_eh[NNODES * EDIM];  // fp16 eigs * sqrt(e^l0)   (3.2 MB)
__device__ float  g_pexp[PTYPES];       // exp(path_emb_w[p])

// ---------------------------------------------------------------------------
// 0) prep: zero histogram, exp tables, scaled fp16 side-copies of k and eigs
// ---------------------------------------------------------------------------
__global__ void k_prep(const float* __restrict__ k,
                       const float* __restrict__ eigs,
                       const float* __restrict__ lambda0,
                       const float* __restrict__ path_w, int n_nodes) {
    int tid = blockIdx.x * blockDim.x + threadIdx.x;
    int stride = gridDim.x * blockDim.x;

    for (int i = tid; i < n_nodes; i += stride) g_cnt[i] = 0;

    const float inv_sqrt_h = 0.08838834764831845f;          // 1/sqrt(128)
    // k * 1/sqrt(H) -> fp16
    int nk4 = n_nodes * (HDIM / 4);
    for (int i = tid; i < nk4; i += stride) {
        float4 f = __ldg(reinterpret_cast<const float4*>(k) + i);
        __half2 lo = __floats2half2_rn(f.x * inv_sqrt_h, f.y * inv_sqrt_h);
        __half2 hi = __floats2half2_rn(f.z * inv_sqrt_h, f.w * inv_sqrt_h);
        uint2 o;
        o.x = *reinterpret_cast<unsigned*>(&lo);
        o.y = *reinterpret_cast<unsigned*>(&hi);
        reinterpret_cast<uint2*>(g_kh)[i] = o;
    }
    // eigs * sqrt(exp(lambda0)) -> fp16  (er*ec then carries exp(lambda0))
    const float sq = sqrtf(expf(__ldg(lambda0)));
    int ne4 = n_nodes * (EDIM / 4);
    for (int i = tid; i < ne4; i += stride) {
        float4 f = __ldg(reinterpret_cast<const float4*>(eigs) + i);
        __half2 lo = __floats2half2_rn(f.x * sq, f.y * sq);
        __half2 hi = __floats2half2_rn(f.z * sq, f.w * sq);
        uint2 o;
        o.x = *reinterpret_cast<unsigned*>(&lo);
        o.y = *reinterpret_cast<unsigned*>(&hi);
        reinterpret_cast<uint2*>(g_eh)[i] = o;
    }

    if (tid < PTYPES) g_pexp[tid] = expf(path_w[tid]);
}

// ---------------------------------------------------------------------------
// 1) histogram of destination rows — 4 edges/thread, vectorized load
// ---------------------------------------------------------------------------
__global__ void k_hist(const int* __restrict__ indices, int n_edges) {
    int t = blockIdx.x * blockDim.x + threadIdx.x;
    int base = t * 4;
    if (base + 4 <= n_edges) {
        int4 r = __ldg(reinterpret_cast<const int4*>(indices) + t);
        atomicAdd(&g_cnt[r.x], 1);
        atomicAdd(&g_cnt[r.y], 1);
        atomicAdd(&g_cnt[r.z], 1);
        atomicAdd(&g_cnt[r.w], 1);
    } else {
        for (int e = base; e < n_edges; e++)
            atomicAdd(&g_cnt[__ldg(indices + e)], 1);
    }
}

// ---------------------------------------------------------------------------
// 2) exclusive scan (single block)
// ---------------------------------------------------------------------------
__global__ void k_scan(int n) {
    __shared__ int part[1024];
    int tid = threadIdx.x;
    int chunk = (n + 1023) / 1024;
    int start = tid * chunk;
    int end   = min(start + chunk, n);
    int s = 0;
    for (int i = start; i < end; i++) s += g_cnt[i];
    part[tid] = s;
    __syncthreads();
    for (int off = 1; off < 1024; off <<= 1) {
        int v = 0;
        if (tid >= off) v = part[tid - off];
        __syncthreads();
        if (tid >= off) part[tid] += v;
        __syncthreads();
    }
    int run = (tid == 0) ? 0 : part[tid - 1];
    for (int i = start; i < end; i++) {
        g_rowptr[i] = run;
        g_rowpos[i] = run;
        run += g_cnt[i];
    }
    if (end == n && start <= n) g_rowptr[n] = run;
}

// ---------------------------------------------------------------------------
// 3) scatter — 4 edges/thread, single packed 4B write per edge
// ---------------------------------------------------------------------------
__global__ void k_scatter(const int* __restrict__ indices,
                          const int* __restrict__ ptype, int n_edges) {
    int t = blockIdx.x * blockDim.x + threadIdx.x;
    int base = t * 4;
    if (base + 4 <= n_edges) {
        int4 r = __ldg(reinterpret_cast<const int4*>(indices) + t);
        int4 c = __ldg(reinterpret_cast<const int4*>(indices + n_edges) + t);
        int4 p = __ldg(reinterpret_cast<const int4*>(ptype) + t);
        int pos;
        pos = atomicAdd(&g_rowpos[r.x], 1); g_col_s[pos] = c.x | (p.x << 24);
        pos = atomicAdd(&g_rowpos[r.y], 1); g_col_s[pos] = c.y | (p.y << 24);
        pos = atomicAdd(&g_rowpos[r.z], 1); g_col_s[pos] = c.z | (p.z << 24);
        pos = atomicAdd(&g_rowpos[r.w], 1); g_col_s[pos] = c.w | (p.w << 24);
    } else {
        for (int e = base; e < n_edges; e++) {
            int row = __ldg(indices + e);
            int col = __ldg(indices + n_edges + e);
            int pt  = __ldg(ptype + e);
            int pos = atomicAdd(&g_rowpos[row], 1);
            g_col_s[pos] = col | (pt << 24);
        }
    }
}

// ---------------------------------------------------------------------------
// 4) pass A (scores): warp per row. z = ks.k_c + er.ec ; e0 = exp(z).
//    Writes g_e0 per edge and per-row denominators. Lean registers -> high occ.
// ---------------------------------------------------------------------------
__global__ void __launch_bounds__(256)
k_score(const float* __restrict__ q, int n_nodes) {
    __shared__ float s_pexp[PTYPES];
    if (threadIdx.x < PTYPES) s_pexp[threadIdx.x] = g_pexp[threadIdx.x];
    __syncthreads();

    int warp = (blockIdx.x * blockDim.x + threadIdx.x) >> 5;
    int lane = threadIdx.x & 31;
    if (warp >= n_nodes) return;
    const int row = warp;
    const int beg = g_rowptr[row];
    const int end = g_rowptr[row + 1];
    if (beg == end) { if (lane == 0) { g_d0[row] = 1.f; g_d1[row] = 1.f; } return; }

    const float inv_sqrt_h = 0.08838834764831845f;
    float4 qv = __ldg(reinterpret_cast<const float4*>(q + (size_t)row * HDIM) + lane);
    qv.x *= inv_sqrt_h; qv.y *= inv_sqrt_h;
    qv.z *= inv_sqrt_h; qv.w *= inv_sqrt_h;
    // note: g_kh already carries 1/sqrt(H)? NO — folded into q here and NOT in kh
    // (kh carries it too would double-apply). See prep: kh carries inv_sqrt_h,
    // so q must NOT. Undo:
    qv.x *= (1.0f / inv_sqrt_h); qv.y *= (1.0f / inv_sqrt_h);
    qv.z *= (1.0f / inv_sqrt_h); qv.w *= (1.0f / inv_sqrt_h);

    float er = (lane < EDIM)
             ? __half2float(__ldg(g_eh + (size_t)row * EDIM + lane)) : 0.f;

    float d0 = 0.f, d1 = 0.f;
    int j = beg;
    for (; j + 4 <= end; j += 4) {
        int pk[4];
        #pragma unroll
        for (int u = 0; u < 4; u++) pk[u] = __ldg(g_col_s + j + u);
        uint2 kr[4];
        float ec[4];
        #pragma unroll
        for (int u = 0; u < 4; u++) {
            int c = pk[u] & 0xFFFFFF;
            kr[u] = __ldg(reinterpret_cast<const uint2*>(g_kh + (size_t)c * HDIM) + lane);
            ec[u] = (lane < EDIM)
                  ? __half2float(__ldg(g_eh + (size_t)c * EDIM + lane)) : 0.f;
        }
        float z[4];
        #pragma unroll
        for (int u = 0; u < 4; u++) {
            float2 k01 = __half22float2(*reinterpret_cast<__half2*>(&kr[u].x));
            float2 k23 = __half22float2(*reinterpret_cast<__half2*>(&kr[u].y));
            z[u] = qv.x * k01.x + qv.y * k01.y
                 + qv.z * k23.x + qv.w * k23.y + er * ec[u];
        }
        #pragma unroll
        for (int o = 16; o > 0; o >>= 1) {
            #pragma unroll
            for (int u = 0; u < 4; u++)
                z[u] += __shfl_xor_sync(0xffffffffu, z[u], o);
        }
        #pragma unroll
        for (int u = 0; u < 4; u++) {
            float e0 = __expf(z[u]);
            d0 += e0;
            d1 += s_pexp[((unsigned)pk[u]) >> 24];
            if (lane == 0) g_e0[j + u] = e0;
        }
    }
    for (; j < end; j++) {
        int pk0 = __ldg(g_col_s + j);
        int c = pk0 & 0xFFFFFF;
        uint2 kr = __ldg(reinterpret_cast<const uint2*>(g_kh + (size_t)c * HDIM) + lane);
        float ec = (lane < EDIM)
                 ? __half2float(__ldg(g_eh + (size_t)c * EDIM + lane)) : 0.f;
        float2 k01 = __half22float2(*reinterpret_cast<__half2*>(&kr.x));
        float2 k23 = __half22float2(*reinterpret_cast<__half2*>(&kr.y));
        float z = qv.x * k01.x + qv.y * k01.y
                + qv.z * k23.x + qv.w * k23.y + er * ec;
        #pragma unroll
        for (int o = 16; o > 0; o >>= 1)
            z += __shfl_xor_sync(0xffffffffu, z, o);
        float e0 = __expf(z);
        d0 += e0;
        d1 += s_pexp[((unsigned)pk0) >> 24];
        if (lane == 0) g_e0[j] = e0;
    }
    if (lane == 0) { g_d0[row] = d0; g_d1[row] = d1; }
}

// ---------------------------------------------------------------------------
// 5) pass B (weighted gather): warp per row. No shfl, no exp — pure stream.
//    out[row] = sum_j (e0_j*i0 + pexp[pt_j]*i1) * v[col_j]
// ---------------------------------------------------------------------------
__global__ void __launch_bounds__(256)
k_gather(const float* __restrict__ v, float* __restrict__ out, int n_nodes) {
    __shared__ float s_pexp[PTYPES];
    if (threadIdx.x < PTYPES) s_pexp[threadIdx.x] = g_pexp[threadIdx.x];
    __syncthreads();

    int warp = (blockIdx.x * blockDim.x + threadIdx.x) >> 5;
    int lane = threadIdx.x & 31;
    if (warp >= n_nodes) return;
    const int row = warp;
    const int beg = g_rowptr[row];
    const int end = g_rowptr[row + 1];

    float4 acc = make_float4(0.f, 0.f, 0.f, 0.f);
    if (beg < end) {
        const float i0 = 0.5f / g_d0[row];
        const float i1 = 0.5f / g_d1[row];
        int j = beg;
        for (; j + 4 <= end; j += 4) {
            int   pk[4];
            float e0[4];
            #pragma unroll
            for (int u = 0; u < 4; u++) {
                pk[u] = __ldg(g_col_s + j + u);
                e0[u] = __ldg(g_e0 + j + u);
            }
            float4 vr[4];
            float  w[4];
            #pragma unroll
            for (int u = 0; u < 4; u++) {
                int c = pk[u] & 0xFFFFFF;
                vr[u] = __ldg(reinterpret_cast<const float4*>(v + (size_t)c * HDIM) + lane);
                w[u]  = e0[u] * i0 + s_pexp[((unsigned)pk[u]) >> 24] * i1;
            }
            #pragma unroll
            for (int u = 0; u < 4; u++) {
                acc.x += w[u] * vr[u].x;
                acc.y += w[u] * vr[u].y;
                acc.z += w[u] * vr[u].z;
                acc.w += w[u] * vr[u].w;
            }
        }
        for (; j < end; j++) {
            int pk0 = __ldg(g_col_s + j);
            int c = pk0 & 0xFFFFFF;
            float w0 = __ldg(g_e0 + j) * i0 + s_pexp[((unsigned)pk0) >> 24] * i1;
            float4 v0 = __ldg(reinterpret_cast<const float4*>(v + (size_t)c * HDIM) + lane);
            acc.x += w0 * v0.x; acc.y += w0 * v0.y;
            acc.z += w0 * v0.z; acc.w += w0 * v0.w;
        }
    }
    reinterpret_cast<float4*>(out + (size_t)row * HDIM)[lane] = acc;
}

// ---------------------------------------------------------------------------
extern "C" void kernel_launch(void* const* d_in, const int* in_sizes, int n_in,
                              void* d_out, int out_size) {
    const float* q       = (const float*)d_in[0];
    const float* k       = (const float*)d_in[1];
    const float* v       = (const float*)d_in[2];
    const float* eigs    = (const float*)d_in[3];
    const float* lambda0 = (const float*)d_in[4];
    const float* path_w  = (const float*)d_in[5];
    const int*   indices = (const int*)d_in[6];
    const int*   ptype   = (const int*)d_in[7];
    float*       out     = (float*)d_out;

    int n_edges = in_sizes[6] / 2;
    int n_nodes = in_sizes[0] / HDIM;
    if (n_edges > EDGES)  n_edges = EDGES;
    if (n_nodes > NNODES) n_nodes = NNODES;

    int eb4 = (n_edges / 4 + 255) / 256 + 1;
    int rb  = (n_nodes * 32 + 255) / 256;

    k_prep<<<2048, 256>>>(k, eigs, lambda0, path_w, n_nodes);
    k_hist<<<eb4, 256>>>(indices, n_edges);
    k_scan<<<1, 1024>>>(n_nodes);
    k_scatter<<<eb4, 256>>>(indices, ptype, n_edges);
    k_score<<<rb, 256>>>(q, n_nodes);
    k_gather<<<rb, 256>>>(v, out, n_nodes);
}

// round 6
// speedup vs baseline: 1.0589x; 1.0589x over previous
#include <cuda_runtime.h>
#include <cuda_fp16.h>
#include <math.h>

#define NNODES 100000
#define EDGES  3200000
#define HDIM   128
#define EDIM   16
#define PTYPES 6

// ---- __device__ scratch (allocations are banned) ----
__device__ int    g_cnt[NNODES];        // degree histogram
__device__ int    g_rowptr[NNODES + 1]; // CSR row pointers
__device__ int    g_rowpos[NNODES];     // scatter cursors
__device__ int    g_col_s[EDGES];       // CSR-ordered packed (col | ptype<<24)
__device__ __half g_kh[NNODES * HDIM];  // fp16 k     (25.6 MB)
__device__ __half g_vh[NNODES * HDIM];  // fp16 v     (25.6 MB)
__device__ __half g_eh[NNODES * EDIM];  // fp16 eigs   (3.2 MB)
__device__ float  g_pexp[PTYPES];       // exp(path_emb_w[p])
__device__ float  g_expl;               // exp(lambda0)

// ---------------------------------------------------------------------------
// 0) prep: zero histogram, exp tables, fp16 copies of k, v, eigs
// ---------------------------------------------------------------------------
__global__ void k_prep(const float* __restrict__ k,
                       const float* __restrict__ v,
                       const float* __restrict__ eigs,
                       const float* __restrict__ lambda0,
                       const float* __restrict__ path_w, int n_nodes) {
    int tid = blockIdx.x * blockDim.x + threadIdx.x;
    int stride = gridDim.x * blockDim.x;

    for (int i = tid; i < n_nodes; i += stride) g_cnt[i] = 0;

    int nk4 = n_nodes * (HDIM / 4);
    for (int i = tid; i < nk4; i += stride) {
        float4 f = __ldg(reinterpret_cast<const float4*>(k) + i);
        __half2 lo = __floats2half2_rn(f.x, f.y);
        __half2 hi = __floats2half2_rn(f.z, f.w);
        uint2 o;
        o.x = *reinterpret_cast<unsigned*>(&lo);
        o.y = *reinterpret_cast<unsigned*>(&hi);
        reinterpret_cast<uint2*>(g_kh)[i] = o;
    }
    for (int i = tid; i < nk4; i += stride) {
        float4 f = __ldg(reinterpret_cast<const float4*>(v) + i);
        __half2 lo = __floats2half2_rn(f.x, f.y);
        __half2 hi = __floats2half2_rn(f.z, f.w);
        uint2 o;
        o.x = *reinterpret_cast<unsigned*>(&lo);
        o.y = *reinterpret_cast<unsigned*>(&hi);
        reinterpret_cast<uint2*>(g_vh)[i] = o;
    }
    int ne4 = n_nodes * (EDIM / 4);
    for (int i = tid; i < ne4; i += stride) {
        float4 f = __ldg(reinterpret_cast<const float4*>(eigs) + i);
        __half2 lo = __floats2half2_rn(f.x, f.y);
        __half2 hi = __floats2half2_rn(f.z, f.w);
        uint2 o;
        o.x = *reinterpret_cast<unsigned*>(&lo);
        o.y = *reinterpret_cast<unsigned*>(&hi);
        reinterpret_cast<uint2*>(g_eh)[i] = o;
    }

    if (tid < PTYPES) g_pexp[tid] = expf(path_w[tid]);
    if (tid == 0)     g_expl = expf(lambda0[0]);
}

// ---------------------------------------------------------------------------
// 1) histogram of destination rows — 8 edges/thread (latency-bound atomics)
// ---------------------------------------------------------------------------
__global__ void k_hist(const int* __restrict__ indices, int n_edges) {
    int t = blockIdx.x * blockDim.x + threadIdx.x;
    int base = t * 8;
    if (base + 8 <= n_edges) {
        int4 a = __ldg(reinterpret_cast<const int4*>(indices) + t * 2);
        int4 b = __ldg(reinterpret_cast<const int4*>(indices) + t * 2 + 1);
        atomicAdd(&g_cnt[a.x], 1); atomicAdd(&g_cnt[a.y], 1);
        atomicAdd(&g_cnt[a.z], 1); atomicAdd(&g_cnt[a.w], 1);
        atomicAdd(&g_cnt[b.x], 1); atomicAdd(&g_cnt[b.y], 1);
        atomicAdd(&g_cnt[b.z], 1); atomicAdd(&g_cnt[b.w], 1);
    } else {
        for (int e = base; e < n_edges; e++)
            atomicAdd(&g_cnt[__ldg(indices + e)], 1);
    }
}

// ---------------------------------------------------------------------------
// 2) exclusive scan (single block)
// ---------------------------------------------------------------------------
__global__ void k_scan(int n) {
    __shared__ int part[1024];
    int tid = threadIdx.x;
    int chunk = (n + 1023) / 1024;
    int start = tid * chunk;
    int end   = min(start + chunk, n);
    int s = 0;
    for (int i = start; i < end; i++) s += g_cnt[i];
    part[tid] = s;
    __syncthreads();
    for (int off = 1; off < 1024; off <<= 1) {
        int v = 0;
        if (tid >= off) v = part[tid - off];
        __syncthreads();
        if (tid >= off) part[tid] += v;
        __syncthreads();
    }
    int run = (tid == 0) ? 0 : part[tid - 1];
    for (int i = start; i < end; i++) {
        g_rowptr[i] = run;
        g_rowpos[i] = run;
        run += g_cnt[i];
    }
    if (end == n && start <= n) g_rowptr[n] = run;
}

// ---------------------------------------------------------------------------
// 3) scatter — 8 edges/thread, single packed 4B write per edge
// ---------------------------------------------------------------------------
__global__ void k_scatter(const int* __restrict__ indices,
                          const int* __restrict__ ptype, int n_edges) {
    int t = blockIdx.x * blockDim.x + threadIdx.x;
    int base = t * 8;
    if (base + 8 <= n_edges) {
        int4 r0 = __ldg(reinterpret_cast<const int4*>(indices) + t * 2);
        int4 r1 = __ldg(reinterpret_cast<const int4*>(indices) + t * 2 + 1);
        int4 c0 = __ldg(reinterpret_cast<const int4*>(indices + n_edges) + t * 2);
        int4 c1 = __ldg(reinterpret_cast<const int4*>(indices + n_edges) + t * 2 + 1);
        int4 p0 = __ldg(reinterpret_cast<const int4*>(ptype) + t * 2);
        int4 p1 = __ldg(reinterpret_cast<const int4*>(ptype) + t * 2 + 1);
        int pos;
        pos = atomicAdd(&g_rowpos[r0.x], 1); g_col_s[pos] = c0.x | (p0.x << 24);
        pos = atomicAdd(&g_rowpos[r0.y], 1); g_col_s[pos] = c0.y | (p0.y << 24);
        pos = atomicAdd(&g_rowpos[r0.z], 1); g_col_s[pos] = c0.z | (p0.z << 24);
        pos = atomicAdd(&g_rowpos[r0.w], 1); g_col_s[pos] = c0.w | (p0.w << 24);
        pos = atomicAdd(&g_rowpos[r1.x], 1); g_col_s[pos] = c1.x | (p1.x << 24);
        pos = atomicAdd(&g_rowpos[r1.y], 1); g_col_s[pos] = c1.y | (p1.y << 24);
        pos = atomicAdd(&g_rowpos[r1.z], 1); g_col_s[pos] = c1.z | (p1.z << 24);
        pos = atomicAdd(&g_rowpos[r1.w], 1); g_col_s[pos] = c1.w | (p1.w << 24);
    } else {
        for (int e = base; e < n_edges; e++) {
            int row = __ldg(indices + e);
            int col = __ldg(indices + n_edges + e);
            int pt  = __ldg(ptype + e);
            int pos = atomicAdd(&g_rowpos[row], 1);
            g_col_s[pos] = col | (pt << 24);
        }
    }
}

// ---------------------------------------------------------------------------
// 4) fused pass: warp per row, single sweep, all gathered operands fp16.
//    out[row] = (0.5/d0) * sum_j e0_j v_j + (0.5/d1) * sum_j pw_j v_j
// ---------------------------------------------------------------------------
__global__ void __launch_bounds__(256)
k_fused(const float* __restrict__ q, float* __restrict__ out, int n_nodes) {
    __shared__ float s_pexp[PTYPES];
    if (threadIdx.x < PTYPES) s_pexp[threadIdx.x] = g_pexp[threadIdx.x];
    __syncthreads();

    int warp = (blockIdx.x * blockDim.x + threadIdx.x) >> 5;
    int lane = threadIdx.x & 31;
    if (warp >= n_nodes) return;
    const int row = warp;
    const int beg = g_rowptr[row];
    const int end = g_rowptr[row + 1];

    float4 acc0 = make_float4(0.f, 0.f, 0.f, 0.f);  // sum e0_j * v_j
    float4 acc1 = make_float4(0.f, 0.f, 0.f, 0.f);  // sum pw_j * v_j
    float  d0 = 0.f, d1 = 0.f;

    if (beg < end) {
        const float inv_sqrt_h = 0.08838834764831845f;  // 1/sqrt(128)
        float4 qv = __ldg(reinterpret_cast<const float4*>(q + (size_t)row * HDIM) + lane);
        qv.x *= inv_sqrt_h; qv.y *= inv_sqrt_h;
        qv.z *= inv_sqrt_h; qv.w *= inv_sqrt_h;
        float er = (lane < EDIM)
                 ? g_expl * __half2float(__ldg(g_eh + (size_t)row * EDIM + lane)) : 0.f;

        int j = beg;
        for (; j + 4 <= end; j += 4) {
            int pk[4];
            #pragma unroll
            for (int u = 0; u < 4; u++) pk[u] = __ldg(g_col_s + j + u);
            uint2 kr[4], vr[4];
            float ec[4];
            #pragma unroll
            for (int u = 0; u < 4; u++) {
                int c = pk[u] & 0xFFFFFF;
                kr[u] = __ldg(reinterpret_cast<const uint2*>(g_kh + (size_t)c * HDIM) + lane);
                vr[u] = __ldg(reinterpret_cast<const uint2*>(g_vh + (size_t)c * HDIM) + lane);
                ec[u] = (lane < EDIM)
                      ? __half2float(__ldg(g_eh + (size_t)c * EDIM + lane)) : 0.f;
            }
            float z[4];
            #pragma unroll
            for (int u = 0; u < 4; u++) {
                float2 k01 = __half22float2(*reinterpret_cast<__half2*>(&kr[u].x));
                float2 k23 = __half22float2(*reinterpret_cast<__half2*>(&kr[u].y));
                z[u] = qv.x * k01.x + qv.y * k01.y
                     + qv.z * k23.x + qv.w * k23.y + er * ec[u];
            }
            #pragma unroll
            for (int o = 16; o > 0; o >>= 1) {
                #pragma unroll
                for (int u = 0; u < 4; u++)
                    z[u] += __shfl_xor_sync(0xffffffffu, z[u], o);
            }
            #pragma unroll
            for (int u = 0; u < 4; u++) {
                float e0 = __expf(z[u]);
                float pw = s_pexp[((unsigned)pk[u]) >> 24];
                d0 += e0;
                d1 += pw;
                float2 v01 = __half22float2(*reinterpret_cast<__half2*>(&vr[u].x));
                float2 v23 = __half22float2(*reinterpret_cast<__half2*>(&vr[u].y));
                acc0.x += e0 * v01.x; acc0.y += e0 * v01.y;
                acc0.z += e0 * v23.x; acc0.w += e0 * v23.y;
                acc1.x += pw * v01.x; acc1.y += pw * v01.y;
                acc1.z += pw * v23.x; acc1.w += pw * v23.y;
            }
        }
        for (; j < end; j++) {
            int pk0 = __ldg(g_col_s + j);
            int c = pk0 & 0xFFFFFF;
            uint2 kr = __ldg(reinterpret_cast<const uint2*>(g_kh + (size_t)c * HDIM) + lane);
            uint2 vr = __ldg(reinterpret_cast<const uint2*>(g_vh + (size_t)c * HDIM) + lane);
            float ec = (lane < EDIM)
                     ? __half2float(__ldg(g_eh + (size_t)c * EDIM + lane)) : 0.f;
            float2 k01 = __half22float2(*reinterpret_cast<__half2*>(&kr.x));
            float2 k23 = __half22float2(*reinterpret_cast<__half2*>(&kr.y));
            float z = qv.x * k01.x + qv.y * k01.y
                    + qv.z * k23.x + qv.w * k23.y + er * ec;
            #pragma unroll
            for (int o = 16; o > 0; o >>= 1)
                z += __shfl_xor_sync(0xffffffffu, z, o);
            float e0 = __expf(z);
            float pw = s_pexp[((unsigned)pk0) >> 24];
            d0 += e0;
            d1 += pw;
            float2 v01 = __half22float2(*reinterpret_cast<__half2*>(&vr.x));
            float2 v23 = __half22float2(*reinterpret_cast<__half2*>(&vr.y));
            acc0.x += e0 * v01.x; acc0.y += e0 * v01.y;
            acc0.z += e0 * v23.x; acc0.w += e0 * v23.y;
            acc1.x += pw * v01.x; acc1.y += pw * v01.y;
            acc1.z += pw * v23.x; acc1.w += pw * v23.y;
        }

        float i0 = 0.5f / d0;
        float i1 = 0.5f / d1;
        acc0.x = i0 * acc0.x + i1 * acc1.x;
        acc0.y = i0 * acc0.y + i1 * acc1.y;
        acc0.z = i0 * acc0.z + i1 * acc1.z;
        acc0.w = i0 * acc0.w + i1 * acc1.w;
    }
    reinterpret_cast<float4*>(out + (size_t)row * HDIM)[lane] = acc0;
}

// ---------------------------------------------------------------------------
extern "C" void kernel_launch(void* const* d_in, const int* in_sizes, int n_in,
                              void* d_out, int out_size) {
    const float* q       = (const float*)d_in[0];
    const float* k       = (const float*)d_in[1];
    const float* v       = (const float*)d_in[2];
    const float* eigs    = (const float*)d_in[3];
    const float* lambda0 = (const float*)d_in[4];
    const float* path_w  = (const float*)d_in[5];
    const int*   indices = (const int*)d_in[6];
    const int*   ptype   = (const int*)d_in[7];
    float*       out     = (float*)d_out;

    int n_edges = in_sizes[6] / 2;
    int n_nodes = in_sizes[0] / HDIM;
    if (n_edges > EDGES)  n_edges = EDGES;
    if (n_nodes > NNODES) n_nodes = NNODES;

    int eb8 = (n_edges / 8 + 255) / 256 + 1;
    int rb  = (n_nodes * 32 + 255) / 256;

    k_prep<<<2048, 256>>>(k, v, eigs, lambda0, path_w, n_nodes);
    k_hist<<<eb8, 256>>>(indices, n_edges);
    k_scan<<<1, 1024>>>(n_nodes);
    k_scatter<<<eb8, 256>>>(indices, ptype, n_edges);
    k_fused<<<rb, 256>>>(q, out, n_nodes);
}